// round 14
// baseline (speedup 1.0000x reference)
#include <cuda_runtime.h>
#include <cuda_bf16.h>
#include <cstdint>
#include <math.h>

#define DIMC   256
#define HEADS  8
#define WSZ    8
#define SHIFTW 4
#define BATCH  16
#define MTOK   (BATCH*64*64)         // 65536 tokens
#define QSCALE 0.17677669529663687f  // 32^-0.5

typedef __nv_bfloat16 bf16;

// -------- scratch (device globals) --------
__device__ bf16  g_x0w[MTOK*DIMC];   // tiled, K=256
__device__ bf16  g_x1w[MTOK*DIMC];   // tiled, K=256
__device__ bf16  g_q  [MTOK*DIMC];   // linear (win, head, n, d)
__device__ bf16  g_k  [MTOK*DIMC];
__device__ bf16  g_v  [MTOK*DIMC];
__device__ bf16  g_ao [MTOK*DIMC];   // tiled, K=256
__device__ float g_x  [MTOK*DIMC];   // residual stream (fp32, linear)
__device__ bf16  g_xln[MTOK*DIMC];   // tiled, K=256
__device__ bf16  g_h  [MTOK*4*DIMC]; // tiled, K=1024
__device__ bf16 g_bWq [DIMC*DIMC];
__device__ bf16 g_bWkv[2*DIMC*DIMC];
__device__ bf16 g_bWp [DIMC*DIMC];
__device__ bf16 g_bW1 [4*DIMC*DIMC];
__device__ bf16 g_bW2 [4*DIMC*DIMC];
__device__ float g_bm[4*8*64*64];    // combined bias+mask table

// -------------------------- helpers ---------------------------------------
__device__ __forceinline__ uint32_t smem_u32(const void* p) {
    return (uint32_t)__cvta_generic_to_shared(p);
}
__device__ __forceinline__ void cp_async16_a(uint32_t smem_dst, const void* gmem_src) {
    asm volatile("cp.async.cg.shared.global [%0], [%1], 16;\n" :: "r"(smem_dst), "l"(gmem_src));
}
__device__ __forceinline__ void cp_commit() { asm volatile("cp.async.commit_group;\n"); }
__device__ __forceinline__ void cp_wait0()  { asm volatile("cp.async.wait_group 0;\n"); }

__device__ __forceinline__ void bulk_g2s(uint32_t dst, const void* src, uint32_t bytes, uint32_t mbar) {
    asm volatile("cp.async.bulk.shared::cta.global.mbarrier::complete_tx::bytes [%0], [%1], %2, [%3];"
                 :: "r"(dst), "l"(src), "r"(bytes), "r"(mbar) : "memory");
}
__device__ __forceinline__ void mbar_init(uint32_t mbar, uint32_t cnt) {
    asm volatile("mbarrier.init.shared.b64 [%0], %1;" :: "r"(mbar), "r"(cnt) : "memory");
}
__device__ __forceinline__ void mbar_expect_tx(uint32_t mbar, uint32_t bytes) {
    asm volatile("mbarrier.arrive.expect_tx.shared.b64 _, [%0], %1;" :: "r"(mbar), "r"(bytes) : "memory");
}
__device__ __forceinline__ void mbar_arrive(uint32_t mbar) {
    asm volatile("mbarrier.arrive.shared.b64 _, [%0];" :: "r"(mbar) : "memory");
}
__device__ __forceinline__ void mbar_wait(uint32_t mbar, uint32_t parity) {
    asm volatile(
        "{\n\t.reg .pred P;\n\t"
        "WL%=:\n\t"
        "mbarrier.try_wait.parity.acquire.cta.shared::cta.b64 P, [%0], %1, 0x989680;\n\t"
        "@P bra WD%=;\n\t"
        "bra.uni WL%=;\n\t"
        "WD%=:\n\t}"
        :: "r"(mbar), "r"(parity) : "memory");
}

__device__ __forceinline__ void mma_bf16(float c[4], const uint32_t a[4], const uint32_t b[2]) {
    asm volatile(
        "mma.sync.aligned.m16n8k16.row.col.f32.bf16.bf16.f32 "
        "{%0,%1,%2,%3}, {%4,%5,%6,%7}, {%8,%9}, {%0,%1,%2,%3};"
        : "+f"(c[0]), "+f"(c[1]), "+f"(c[2]), "+f"(c[3])
        : "r"(a[0]), "r"(a[1]), "r"(a[2]), "r"(a[3]), "r"(b[0]), "r"(b[1]));
}
__device__ __forceinline__ void ldsm4(uint32_t& r0, uint32_t& r1, uint32_t& r2, uint32_t& r3, uint32_t addr) {
    asm volatile("ldmatrix.sync.aligned.m8n8.x4.shared.b16 {%0,%1,%2,%3}, [%4];"
        : "=r"(r0), "=r"(r1), "=r"(r2), "=r"(r3) : "r"(addr));
}
__device__ __forceinline__ void ldsm4t(uint32_t& r0, uint32_t& r1, uint32_t& r2, uint32_t& r3, uint32_t addr) {
    asm volatile("ldmatrix.sync.aligned.m8n8.x4.trans.shared.b16 {%0,%1,%2,%3}, [%4];"
        : "=r"(r0), "=r"(r1), "=r"(r2), "=r"(r3) : "r"(addr));
}
__device__ __forceinline__ uint32_t pack_bf16(float lo, float hi) {
    uint32_t r;
    asm("cvt.rn.bf16x2.f32 %0, %1, %2;" : "=r"(r) : "f"(hi), "f"(lo));
    return r;
}
__device__ __forceinline__ float warp_sum(float v) {
    #pragma unroll
    for (int o = 16; o; o >>= 1) v += __shfl_xor_sync(0xffffffffu, v, o);
    return v;
}

// ---------------- build combined bias+mask table ---------------------------
__global__ void __launch_bounds__(256) build_bm(const float* __restrict__ rpb)
{
    int cls  = blockIdx.y;
    int head = blockIdx.z;
    int lastR = cls & 1, lastC = (cls >> 1) & 1;
    for (int e = blockIdx.x * 256 + threadIdx.x; e < 4096; e += gridDim.x * 256) {
        int i = e >> 6, j = e & 63;
        int ri = i >> 3, ci = i & 7, rj = j >> 3, cj = j & 7;
        int rel = (ri - rj + 7) * 15 + (ci - cj + 7);
        float a = rpb[rel * 8 + head];
        int liR = lastR ? (ri < 4 ? 1 : 2) : 0;
        int liC = lastC ? (ci < 4 ? 1 : 2) : 0;
        int ljR = lastR ? (rj < 4 ? 1 : 2) : 0;
        int ljC = lastC ? (cj < 4 ? 1 : 2) : 0;
        if (liR * 3 + liC != ljR * 3 + ljC) a -= 100.f;
        g_bm[((cls * 8 + head) << 12) + e] = a;
    }
}

// ---------------------- weight conversion fp32 -> bf16 (tiled) -------------
__global__ void __launch_bounds__(256) convert_weights(
    const float* __restrict__ Wq, const float* __restrict__ Wkv,
    const float* __restrict__ Wp, const float* __restrict__ W1,
    const float* __restrict__ W2)
{
    int which = blockIdx.y;
    const float* src; bf16* dst; int N, K;
    if      (which == 0) { src = Wq;  dst = g_bWq;  N = 256;  K = 256;  }
    else if (which == 1) { src = Wkv; dst = g_bWkv; N = 512;  K = 256;  }
    else if (which == 2) { src = Wp;  dst = g_bWp;  N = 256;  K = 256;  }
    else if (which == 3) { src = W1;  dst = g_bW1;  N = 1024; K = 256;  }
    else                 { src = W2;  dst = g_bW2;  N = 256;  K = 1024; }
    int Kp8 = K >> 3;
    int nchunks = N * Kp8;
    const float4* src4 = (const float4*)src;
    char* dc = (char*)dst;
    for (int f = blockIdx.x * 256 + threadIdx.x; f < nchunks; f += gridDim.x * 256) {
        int nrow = f / Kp8;
        int ch0  = (f - nrow * Kp8) * 8;
        float4 v0 = src4[f * 2], v1 = src4[f * 2 + 1];
        uint4 o;
        o.x = pack_bf16(v0.x, v0.y); o.y = pack_bf16(v0.z, v0.w);
        o.z = pack_bf16(v1.x, v1.y); o.w = pack_bf16(v1.z, v1.w);
        int row = nrow & 127;
        size_t off = ((size_t)(nrow >> 7) * (K >> 5) + (ch0 >> 5)) * 8192
                   + row * 64 + ((((ch0 >> 3) & 3) ^ ((row >> 1) & 3)) * 16);
        *(uint4*)(dc + off) = o;
    }
}

// ---------- LN + cyclic shift + window partition (warp/token, tiled out) ---
__global__ void __launch_bounds__(256) ln_shift_part(
    const float* __restrict__ x0, const float* __restrict__ x1,
    const float* __restrict__ g0, const float* __restrict__ b0,
    const float* __restrict__ g1, const float* __restrict__ b1)
{
    int warp = threadIdx.x >> 5, lane = threadIdx.x & 31;
    int outTok = blockIdx.x * 8 + warp;
    int which  = blockIdx.y;
    int win = outTok >> 6, n = outTok & 63;
    int b   = win >> 6,  nw = win & 63;
    int y = ((nw >> 3) * WSZ + (n >> 3) + SHIFTW) & 63;
    int x = ((nw & 7) * WSZ + (n & 7) + SHIFTW) & 63;
    const float4* src4 = (const float4*)((which ? x1 : x0) + (size_t)(b * 4096 + y * 64 + x) * DIMC);
    char* dstc = (char*)(which ? g_x1w : g_x0w);
    const float4* gg4 = (const float4*)(which ? g1 : g0);
    const float4* bb4 = (const float4*)(which ? b1 : b0);

    float4 v0 = src4[lane * 2], v1 = src4[lane * 2 + 1];
    float s = v0.x + v0.y + v0.z + v0.w + v1.x + v1.y + v1.z + v1.w;
    float mean = warp_sum(s) * (1.f / 256.f);
    float d0 = v0.x - mean, d1 = v0.y - mean, d2 = v0.z - mean, d3 = v0.w - mean;
    float d4 = v1.x - mean, d5 = v1.y - mean, d6 = v1.z - mean, d7 = v1.w - mean;
    float vv = d0*d0 + d1*d1 + d2*d2 + d3*d3 + d4*d4 + d5*d5 + d6*d6 + d7*d7;
    float r = rsqrtf(warp_sum(vv) * (1.f / 256.f) + 1e-5f);
    float4 ga = gg4[lane * 2], gb = gg4[lane * 2 + 1];
    float4 ba = bb4[lane * 2], bb = bb4[lane * 2 + 1];
    uint4 o;
    o.x = pack_bf16(d0 * r * ga.x + ba.x, d1 * r * ga.y + ba.y);
    o.y = pack_bf16(d2 * r * ga.z + ba.z, d3 * r * ga.w + ba.w);
    o.z = pack_bf16(d4 * r * gb.x + bb.x, d5 * r * gb.y + bb.y);
    o.w = pack_bf16(d6 * r * gb.z + bb.z, d7 * r * gb.w + bb.w);
    int row = outTok & 127;
    size_t off = ((size_t)(outTok >> 7) * 8 + (lane >> 2)) * 8192
               + row * 64 + (((lane & 3) ^ ((row >> 1) & 3)) * 16);
    *(uint4*)(dstc + off) = o;
}

// ---------------- plain LN of g_x (fp32) -> g_xln (tiled bf16) -------------
__global__ void __launch_bounds__(256) ln_plain(
    const float* __restrict__ g2, const float* __restrict__ b2)
{
    int warp = threadIdx.x >> 5, lane = threadIdx.x & 31;
    int tok = blockIdx.x * 8 + warp;
    const float4* src4 = (const float4*)(g_x + (size_t)tok * DIMC);
    char* dstc = (char*)g_xln;
    const float4* gg4 = (const float4*)g2;
    const float4* bb4 = (const float4*)b2;

    float4 v0 = src4[lane * 2], v1 = src4[lane * 2 + 1];
    float s = v0.x + v0.y + v0.z + v0.w + v1.x + v1.y + v1.z + v1.w;
    float mean = warp_sum(s) * (1.f / 256.f);
    float d0 = v0.x - mean, d1 = v0.y - mean, d2 = v0.z - mean, d3 = v0.w - mean;
    float d4 = v1.x - mean, d5 = v1.y - mean, d6 = v1.z - mean, d7 = v1.w - mean;
    float vv = d0*d0 + d1*d1 + d2*d2 + d3*d3 + d4*d4 + d5*d5 + d6*d6 + d7*d7;
    float r = rsqrtf(warp_sum(vv) * (1.f / 256.f) + 1e-5f);
    float4 ga = gg4[lane * 2], gb = gg4[lane * 2 + 1];
    float4 ba = bb4[lane * 2], bb = bb4[lane * 2 + 1];
    uint4 o;
    o.x = pack_bf16(d0 * r * ga.x + ba.x, d1 * r * ga.y + ba.y);
    o.y = pack_bf16(d2 * r * ga.z + ba.z, d3 * r * ga.w + ba.w);
    o.z = pack_bf16(d4 * r * gb.x + bb.x, d5 * r * gb.y + bb.y);
    o.w = pack_bf16(d6 * r * gb.z + bb.z, d7 * r * gb.w + bb.w);
    int row = tok & 127;
    size_t off = ((size_t)(tok >> 7) * 8 + (lane >> 2)) * 8192
               + row * 64 + (((lane & 3) ^ ((row >> 1) & 3)) * 16);
    *(uint4*)(dstc + off) = o;
}

// ----------------------- bf16 tensor-core GEMMs ----------------------------
#define GEMM_SMEM (3*32768)

template<int MODE>
__device__ __forceinline__ void emit_pair(int m, int c0, float v0, float v1,
    float b0, float b1, const float* __restrict__ extra, float* __restrict__ out)
{
    v0 += b0;
    v1 += b1;
    if (MODE == 0) {
        v0 *= QSCALE; v1 *= QSCALE;
        int win = m >> 6, n = m & 63, hd = c0 >> 5, d = c0 & 31;
        uint32_t* p = (uint32_t*)g_q + ((((size_t)win * 8 + hd) * 64 + n) * 32 + d) / 2;
        *p = pack_bf16(v0, v1);
    } else if (MODE == 1) {
        int win = m >> 6, n = m & 63;
        int c2 = c0 & 255, hd = c2 >> 5, d = c2 & 31;
        size_t idx = ((((size_t)win * 8 + hd) * 64 + n) * 32 + d) / 2;
        uint32_t* p = (c0 < 256 ? (uint32_t*)g_k : (uint32_t*)g_v) + idx;
        *p = pack_bf16(v0, v1);
    } else if (MODE == 2) {
        int win = m >> 6, n = m & 63;
        int b = win >> 6, nw = win & 63;
        int y = ((nw >> 3) * WSZ + (n >> 3) + SHIFTW) & 63;
        int x = ((nw & 7) * WSZ + (n & 7) + SHIFTW) & 63;
        size_t t = ((size_t)(b * 4096 + y * 64 + x)) * DIMC + c0;
        float2 e = *(const float2*)&extra[t];
        *(float2*)&g_x[t] = make_float2(e.x + v0, e.y + v1);
    } else if (MODE == 3) {
        v0 = 0.5f * v0 * (1.f + erff(v0 * 0.70710678118654752f));
        v1 = 0.5f * v1 * (1.f + erff(v1 * 0.70710678118654752f));
        int row = m & 127;
        size_t off = ((size_t)(m >> 7) * 32 + (c0 >> 5)) * 8192 + row * 64
                   + ((((c0 >> 3) & 3) ^ ((row >> 1) & 3)) * 16) + (c0 & 7) * 2;
        *(uint32_t*)((char*)g_h + off) = pack_bf16(v0, v1);
    } else {
        size_t t = (size_t)m * DIMC + c0;
        float2 r = *(const float2*)&g_x[t];
        *(float2*)&out[t] = make_float2(r.x + v0, r.y + v1);
    }
}

// shared mainloop (BK=64, 3-slot bulk ring). Returns with acc filled.
struct GemmCtx {
    int rA, rB, aCh, bCh, aSwz, bSwz;
    uint32_t Sb, mbF, mbE;
};

__device__ __forceinline__ void gemm_mainloop(
    const GemmCtx& cx, const char* Ac, const char* Wc,
    size_t aT0, size_t wT0, int nK, int tid, float acc[4][4][4])
{
    if (tid == 0) {
        #pragma unroll
        for (int st = 0; st < 3; st++) {
            mbar_expect_tx(cx.mbF + st * 8, 32768);
            bulk_g2s(cx.Sb + st * 32768,         Ac + (aT0 + st * 2) * 8192, 16384, cx.mbF + st * 8);
            bulk_g2s(cx.Sb + st * 32768 + 16384, Wc + (wT0 + st * 2) * 8192, 16384, cx.mbF + st * 8);
        }
    }
    for (int s = 0; s < nK; ++s) {
        int q = s / 3;
        int slot = s - q * 3;
        mbar_wait(cx.mbF + slot * 8, (uint32_t)(q & 1));

        uint32_t stA = cx.Sb + slot * 32768;
        uint32_t stW = stA + 16384;
        #pragma unroll
        for (int ts = 0; ts < 2; ++ts) {
            uint32_t tA = stA + ts * 8192;
            uint32_t tW = stW + ts * 8192;
            #pragma unroll
            for (int kk = 0; kk < 2; ++kk) {
                uint32_t aF[4][4], bF[4][2];
                uint32_t aOff = ((kk * 2 + cx.aCh) ^ cx.aSwz) * 16;
                uint32_t bOff = ((kk * 2 + cx.bCh) ^ cx.bSwz) * 16;
                #pragma unroll
                for (int mi = 0; mi < 4; mi++)
                    ldsm4(aF[mi][0], aF[mi][1], aF[mi][2], aF[mi][3],
                          tA + (cx.rA + mi * 16) * 64 + aOff);
                ldsm4(bF[0][0], bF[0][1], bF[1][0], bF[1][1], tW + cx.rB * 64 + bOff);
                ldsm4(bF[2][0], bF[2][1], bF[3][0], bF[3][1], tW + (cx.rB + 16) * 64 + bOff);
                #pragma unroll
                for (int mi = 0; mi < 4; mi++)
                    #pragma unroll
                    for (int ni = 0; ni < 4; ni++)
                        mma_bf16(acc[mi][ni], aF[mi], bF[ni]);
            }
        }
        mbar_arrive(cx.mbE + slot * 8);
        if (tid == 0 && s + 3 < nK) {
            mbar_wait(cx.mbE + slot * 8, (uint32_t)(q & 1));
            mbar_expect_tx(cx.mbF + slot * 8, 32768);
            bulk_g2s(cx.Sb + slot * 32768,         Ac + (aT0 + (s + 3) * 2) * 8192, 16384, cx.mbF + slot * 8);
            bulk_g2s(cx.Sb + slot * 32768 + 16384, Wc + (wT0 + (s + 3) * 2) * 8192, 16384, cx.mbF + slot * 8);
        }
    }
}

__device__ __forceinline__ GemmCtx make_ctx(int tid, bf16* sm, uint64_t* s_full, uint64_t* s_empty) {
    int lane = tid & 31, warp = tid >> 5;
    int mWarp = (warp >> 2) * 64;
    int nWarp = (warp & 3) * 32;
    int mm = lane >> 3, r8 = lane & 7;
    GemmCtx cx;
    cx.rA = mWarp + (mm & 1) * 8 + r8;
    cx.rB = nWarp + (mm >> 1) * 8 + r8;
    cx.aCh = mm >> 1;
    cx.bCh = mm & 1;
    cx.aSwz = (cx.rA >> 1) & 3;
    cx.bSwz = (cx.rB >> 1) & 3;
    cx.Sb  = smem_u32(sm);
    cx.mbF = smem_u32(s_full);
    cx.mbE = smem_u32(s_empty);
    if (tid == 0) {
        #pragma unroll
        for (int st = 0; st < 3; st++) {
            mbar_init(cx.mbF + st * 8, 1);
            mbar_init(cx.mbE + st * 8, 256);
        }
    }
    __syncthreads();
    return cx;
}

template<int MODE>
__global__ void __launch_bounds__(256, 2) mma_gemm(
    const bf16* __restrict__ W, const float* __restrict__ bias,
    int K, const float* __restrict__ extra, float* __restrict__ out)
{
    extern __shared__ bf16 sm[];
    __shared__ uint64_t s_full[3];
    __shared__ uint64_t s_empty[3];
    const bf16* A = (MODE == 2) ? g_ao :
                    (MODE == 3) ? g_xln : g_h;

    int tid  = threadIdx.x;
    int lane = tid & 31, warp = tid >> 5;
    int gr = lane >> 2, lc = lane & 3;
    GemmCtx cx = make_ctx(tid, sm, s_full, s_empty);

    int rowBase = blockIdx.y * 128;
    int colBase = blockIdx.x * 128;
    int nK = K >> 6;
    float acc[4][4][4];
    #pragma unroll
    for (int mi = 0; mi < 4; mi++)
        #pragma unroll
        for (int ni = 0; ni < 4; ni++)
            #pragma unroll
            for (int e = 0; e < 4; e++) acc[mi][ni][e] = 0.f;

    gemm_mainloop(cx, (const char*)A, (const char*)W,
                  (size_t)blockIdx.y * (K >> 5), (size_t)blockIdx.x * (K >> 5),
                  nK, tid, acc);

    int mWarp = (warp >> 2) * 64;
    int nWarp = (warp & 3) * 32;
    float2 bN[4];
    #pragma unroll
    for (int ni = 0; ni < 4; ni++)
        bN[ni] = __ldg((const float2*)&bias[colBase + nWarp + ni * 8 + lc * 2]);

    #pragma unroll
    for (int mi = 0; mi < 4; mi++) {
        int r0 = rowBase + mWarp + mi * 16 + gr;
        #pragma unroll
        for (int ni = 0; ni < 4; ni++) {
            int c0 = colBase + nWarp + ni * 8 + lc * 2;
            emit_pair<MODE>(r0,     c0, acc[mi][ni][0], acc[mi][ni][1], bN[ni].x, bN[ni].y, extra, out);
            emit_pair<MODE>(r0 + 8, c0, acc[mi][ni][2], acc[mi][ni][3], bN[ni].x, bN[ni].y, extra, out);
        }
    }
}

// fused q + kv projection: CTAs [0,1024) do q, [1024,3072) do kv
__global__ void __launch_bounds__(256, 2) mma_gemm_qkv(
    const bf16* __restrict__ Wq, const float* __restrict__ bq,
    const bf16* __restrict__ Wkv, const float* __restrict__ bkv)
{
    extern __shared__ bf16 sm[];
    __shared__ uint64_t s_full[3];
    __shared__ uint64_t s_empty[3];

    int tid  = threadIdx.x;
    int lane = tid & 31, warp = tid >> 5;
    int gr = lane >> 2, lc = lane & 3;
    GemmCtx cx = make_ctx(tid, sm, s_full, s_empty);

    bool isQ = blockIdx.x < 1024;
    int bid  = isQ ? blockIdx.x : blockIdx.x - 1024;
    const bf16* A = isQ ? g_x1w : g_x0w;
    const bf16* W = isQ ? Wq : Wkv;
    const float* bias = isQ ? bq : bkv;
    int tx = isQ ? (bid & 1) : (bid & 3);
    int ty = isQ ? (bid >> 1) : (bid >> 2);
    int rowBase = ty * 128;
    int colBase = tx * 128;

    float acc[4][4][4];
    #pragma unroll
    for (int mi = 0; mi < 4; mi++)
        #pragma unroll
        for (int ni = 0; ni < 4; ni++)
            #pragma unroll
            for (int e = 0; e < 4; e++) acc[mi][ni][e] = 0.f;

    gemm_mainloop(cx, (const char*)A, (const char*)W,
                  (size_t)ty * 8, (size_t)tx * 8, 4, tid, acc);

    int mWarp = (warp >> 2) * 64;
    int nWarp = (warp & 3) * 32;
    float2 bN[4];
    #pragma unroll
    for (int ni = 0; ni < 4; ni++)
        bN[ni] = __ldg((const float2*)&bias[colBase + nWarp + ni * 8 + lc * 2]);

    if (isQ) {
        #pragma unroll
        for (int mi = 0; mi < 4; mi++) {
            int r0 = rowBase + mWarp + mi * 16 + gr;
            #pragma unroll
            for (int ni = 0; ni < 4; ni++) {
                int c0 = colBase + nWarp + ni * 8 + lc * 2;
                emit_pair<0>(r0,     c0, acc[mi][ni][0], acc[mi][ni][1], bN[ni].x, bN[ni].y, nullptr, nullptr);
                emit_pair<0>(r0 + 8, c0, acc[mi][ni][2], acc[mi][ni][3], bN[ni].x, bN[ni].y, nullptr, nullptr);
            }
        }
    } else {
        #pragma unroll
        for (int mi = 0; mi < 4; mi++) {
            int r0 = rowBase + mWarp + mi * 16 + gr;
            #pragma unroll
            for (int ni = 0; ni < 4; ni++) {
                int c0 = colBase + nWarp + ni * 8 + lc * 2;
                emit_pair<1>(r0,     c0, acc[mi][ni][0], acc[mi][ni][1], bN[ni].x, bN[ni].y, nullptr, nullptr);
                emit_pair<1>(r0 + 8, c0, acc[mi][ni][2], acc[mi][ni][3], bN[ni].x, bN[ni].y, nullptr, nullptr);
            }
        }
    }
}

// ------------- tensor-core attention: one CTA per window (512 thr) ---------
// warp w: head = w & 7, half = w >> 3. K/V staged once per window per head
// (each half-warp pair loads its half of rows).
#define ATTN_HEAD_BYTES 9216          // 4096 (K) + 5120 (V)
#define ATTN_SMEM (8*ATTN_HEAD_BYTES) // 73728
__global__ void __launch_bounds__(512, 1) attn_kernel()
{
    extern __shared__ char smattn[];

    int win  = blockIdx.x;
    int tid  = threadIdx.x;
    int lane = tid & 31, w = tid >> 5;
    int head = w & 7, half = w >> 3;
    int gr = lane >> 2, lc = lane & 3;

    size_t hb = ((size_t)win * 8 + head) * 64 * 32;
    const uint32_t* q32 = (const uint32_t*)(g_q + hb);

    uint32_t ksB = smem_u32(smattn) + head * ATTN_HEAD_BYTES;
    uint32_t vsB = ksB + 4096;

    // each warp stages its half of K and V for its head
    {
        const bf16* ksrc = g_k + hb;
        const bf16* vsrc = g_v + hb;
        #pragma unroll
        for (int it = 0; it < 4; it++) {
            int c = half * 128 + it * 32 + lane;
            int row = c >> 2, k8 = (c & 3) * 8;
            uint32_t dst = ksB + row * 64 + ((((c & 3) ^ ((row >> 1) & 3))) * 16);
            cp_async16_a(dst, ksrc + row * 32 + k8);
        }
        #pragma unroll
        for (int it = 0; it < 4; it++) {
            int c = half * 128 + it * 32 + lane;
            int row = c >> 2, k8 = (c & 3) * 8;
            cp_async16_a(vsB + row * 80 + k8 * 2, vsrc + row * 32 + k8);
        }
        cp_commit();
    }
    cp_wait0();
    __syncthreads();

    float sacc[2][8][4];
    #pragma unroll
    for (int mt = 0; mt < 2; mt++)
        #pragma unroll
        for (int nt = 0; nt < 8; nt++)
            #pragma unroll
            for (int e = 0; e < 4; e++) sacc[mt][nt][e] = 0.f;

    int mm = lane >> 3, r8 = lane & 7;
    int rowK16 = (mm >> 1) * 8 + r8;
    int bCh = mm & 1;

    #pragma unroll
    for (int kt = 0; kt < 2; kt++) {
        uint32_t aQ[2][4];
        #pragma unroll
        for (int mt = 0; mt < 2; mt++) {
            int i0 = half * 32 + mt * 16 + gr;
            aQ[mt][0] = q32[i0 * 16 + 8 * kt + lc];
            aQ[mt][1] = q32[(i0 + 8) * 16 + 8 * kt + lc];
            aQ[mt][2] = q32[i0 * 16 + 8 * kt + lc + 4];
            aQ[mt][3] = q32[(i0 + 8) * 16 + 8 * kt + lc + 4];
        }
        uint32_t bK[8][2];
        #pragma unroll
        for (int p = 0; p < 4; p++) {
            int fr = p * 16 + rowK16;
            uint32_t off = ((uint32_t)((kt * 2 + bCh) ^ ((fr >> 1) & 3))) * 16;
            ldsm4(bK[2*p][0], bK[2*p][1], bK[2*p+1][0], bK[2*p+1][1],
                  ksB + fr * 64 + off);
        }
        #pragma unroll
        for (int mt = 0; mt < 2; mt++)
            #pragma unroll
            for (int nt = 0; nt < 8; nt++)
                mma_bf16(sacc[mt][nt], aQ[mt], bK[nt]);
    }

    // ---- add precomputed bias+mask table ----
    int nw  = win & 63;
    int cls = (((nw >> 3) == 7) ? 1 : 0) | (((nw & 7) == 7) ? 2 : 0);
    const float* T = g_bm + ((cls * 8 + head) << 12);
    #pragma unroll
    for (int mt = 0; mt < 2; mt++) {
        #pragma unroll
        for (int re = 0; re < 2; re++) {
            int i = half * 32 + mt * 16 + gr + 8 * re;
            const float2* Trow = (const float2*)(T + i * 64) + lc;
            #pragma unroll
            for (int nt = 0; nt < 8; nt++) {
                float2 t = __ldg(&Trow[nt * 4]);
                sacc[mt][nt][re * 2]     += t.x;
                sacc[mt][nt][re * 2 + 1] += t.y;
            }
        }
    }

    float inv[2][2];
    #pragma unroll
    for (int mt = 0; mt < 2; mt++) {
        #pragma unroll
        for (int re = 0; re < 2; re++) {
            float mx = -1e30f;
            #pragma unroll
            for (int nt = 0; nt < 8; nt++) {
                mx = fmaxf(mx, sacc[mt][nt][re * 2]);
                mx = fmaxf(mx, sacc[mt][nt][re * 2 + 1]);
            }
            mx = fmaxf(mx, __shfl_xor_sync(0xffffffffu, mx, 1));
            mx = fmaxf(mx, __shfl_xor_sync(0xffffffffu, mx, 2));
            float sm = 0.f;
            #pragma unroll
            for (int nt = 0; nt < 8; nt++) {
                float e0 = __expf(sacc[mt][nt][re * 2]     - mx);
                float e1 = __expf(sacc[mt][nt][re * 2 + 1] - mx);
                sacc[mt][nt][re * 2]     = e0;
                sacc[mt][nt][re * 2 + 1] = e1;
                sm += e0 + e1;
            }
            sm += __shfl_xor_sync(0xffffffffu, sm, 1);
            sm += __shfl_xor_sync(0xffffffffu, sm, 2);
            inv[mt][re] = 1.f / sm;
        }
    }

    int vmm = lane >> 3, vr8 = lane & 7;
    int vRow = (vmm & 1) * 8 + vr8, vNd = vmm >> 1;

    float oacc[2][4][4];
    #pragma unroll
    for (int mt = 0; mt < 2; mt++)
        #pragma unroll
        for (int nt = 0; nt < 4; nt++)
            #pragma unroll
            for (int e = 0; e < 4; e++) oacc[mt][nt][e] = 0.f;

    #pragma unroll
    for (int kt = 0; kt < 4; kt++) {
        uint32_t aP[2][4];
        #pragma unroll
        for (int mt = 0; mt < 2; mt++) {
            aP[mt][0] = pack_bf16(sacc[mt][2 * kt][0],     sacc[mt][2 * kt][1]);
            aP[mt][1] = pack_bf16(sacc[mt][2 * kt][2],     sacc[mt][2 * kt][3]);
            aP[mt][2] = pack_bf16(sacc[mt][2 * kt + 1][0], sacc[mt][2 * kt + 1][1]);
            aP[mt][3] = pack_bf16(sacc[mt][2 * kt + 1][2], sacc[mt][2 * kt + 1][3]);
        }
        uint32_t bV[4][2];
        #pragma unroll
        for (int p = 0; p < 2; p++) {
            uint32_t addr = vsB + (((16 * kt + vRow) * 40) + (p * 2 + vNd) * 8) * 2;
            ldsm4t(bV[2*p][0], bV[2*p][1], bV[2*p+1][0], bV[2*p+1][1], addr);
        }
        #pragma unroll
        for (int mt = 0; mt < 2; mt++)
            #pragma unroll
            for (int nt = 0; nt < 4; nt++)
                mma_bf16(oacc[mt][nt], aP[mt], bV[nt]);
    }

    // epilogue: normalize, pack, store to TILED g_ao
    char* aoc = (char*)g_ao;
    #pragma unroll
    for (int mt = 0; mt < 2; mt++) {
        int i0 = half * 32 + mt * 16 + gr;
        int row0 = (win & 1) * 64 + i0;
        int sw = (row0 >> 1) & 3;
        size_t base = ((size_t)(win >> 1) * 8 + head) * 8192 + (size_t)row0 * 64 + lc * 4;
        float v0 = inv[mt][0], v1 = inv[mt][1];
        #pragma unroll
        for (int nt = 0; nt < 4; nt++) {
            uint32_t p0 = pack_bf16(oacc[mt][nt][0] * v0, oacc[mt][nt][1] * v0);
            uint32_t p1 = pack_bf16(oacc[mt][nt][2] * v1, oacc[mt][nt][3] * v1);
            size_t off = base + (size_t)((nt ^ sw) * 16);
            *(uint32_t*)(aoc + off)       = p0;
            *(uint32_t*)(aoc + off + 512) = p1;   // +8 rows * 64B
        }
    }
}

// ------------------------------- launcher ----------------------------------
extern "C" void kernel_launch(void* const* d_in, const int* in_sizes, int n_in,
                              void* d_out, int out_size)
{
    const float* x0   = (const float*)d_in[0];
    const float* x1   = (const float*)d_in[1];
    const float* g1_0 = (const float*)d_in[2];
    const float* b1_0 = (const float*)d_in[3];
    const float* g1_1 = (const float*)d_in[4];
    const float* b1_1 = (const float*)d_in[5];
    const float* Wq   = (const float*)d_in[6];
    const float* bq   = (const float*)d_in[7];
    const float* Wkv  = (const float*)d_in[8];
    const float* bkv  = (const float*)d_in[9];
    const float* rpb  = (const float*)d_in[10];
    const float* Wp   = (const float*)d_in[11];
    const float* bp   = (const float*)d_in[12];
    const float* g2   = (const float*)d_in[13];
    const float* b2   = (const float*)d_in[14];
    const float* Wfc1 = (const float*)d_in[15];
    const float* bfc1 = (const float*)d_in[16];
    const float* Wfc2 = (const float*)d_in[17];
    const float* bfc2 = (const float*)d_in[18];
    float* out = (float*)d_out;

    bf16 *bWq, *bWkv, *bWp, *bW1, *bW2;
    cudaGetSymbolAddress((void**)&bWq,  g_bWq);
    cudaGetSymbolAddress((void**)&bWkv, g_bWkv);
    cudaGetSymbolAddress((void**)&bWp,  g_bWp);
    cudaGetSymbolAddress((void**)&bW1,  g_bW1);
    cudaGetSymbolAddress((void**)&bW2,  g_bW2);

    cudaFuncSetAttribute(mma_gemm_qkv, cudaFuncAttributeMaxDynamicSharedMemorySize, GEMM_SMEM);
    cudaFuncSetAttribute(mma_gemm<2>, cudaFuncAttributeMaxDynamicSharedMemorySize, GEMM_SMEM);
    cudaFuncSetAttribute(mma_gemm<3>, cudaFuncAttributeMaxDynamicSharedMemorySize, GEMM_SMEM);
    cudaFuncSetAttribute(mma_gemm<4>, cudaFuncAttributeMaxDynamicSharedMemorySize, GEMM_SMEM);
    cudaFuncSetAttribute(attn_kernel, cudaFuncAttributeMaxDynamicSharedMemorySize, ATTN_SMEM);

    build_bm<<<dim3(4, 4, 8), 256>>>(rpb);
    convert_weights<<<dim3(128, 5), 256>>>(Wq, Wkv, Wp, Wfc1, Wfc2);
    ln_shift_part<<<dim3(MTOK / 8, 2), 256>>>(x0, x1, g1_0, b1_0, g1_1, b1_1);
    mma_gemm_qkv<<<3072, 256, GEMM_SMEM>>>(bWq, bq, bWkv, bkv);
    attn_kernel<<<1024, 512, ATTN_SMEM>>>();
    mma_gemm<2><<<dim3(2, 512), 256, GEMM_SMEM>>>(bWp,  bp,   256,  x1,      nullptr);
    ln_plain<<<MTOK / 8, 256>>>(g2, b2);
    mma_gemm<3><<<dim3(8, 512), 256, GEMM_SMEM>>>(bW1,  bfc1, 256,  nullptr, nullptr);
    mma_gemm<4><<<dim3(2, 512), 256, GEMM_SMEM>>>(bW2,  bfc2, 1024, nullptr, out);
}

// round 15
// speedup vs baseline: 1.0132x; 1.0132x over previous
#include <cuda_runtime.h>
#include <cuda_bf16.h>
#include <cstdint>
#include <math.h>

#define DIMC   256
#define HEADS  8
#define WSZ    8
#define SHIFTW 4
#define BATCH  16
#define MTOK   (BATCH*64*64)         // 65536 tokens
#define QSCALE 0.17677669529663687f  // 32^-0.5

typedef __nv_bfloat16 bf16;

// -------- scratch (device globals) --------
__device__ bf16  g_x0w[MTOK*DIMC];   // tiled, K=256
__device__ bf16  g_x1w[MTOK*DIMC];   // tiled, K=256
__device__ bf16  g_q  [MTOK*DIMC];   // linear (win, head, n, d)
__device__ bf16  g_k  [MTOK*DIMC];
__device__ bf16  g_v  [MTOK*DIMC];
__device__ bf16  g_ao [MTOK*DIMC];   // tiled, K=256
__device__ float g_x  [MTOK*DIMC];   // residual stream (fp32, linear)
__device__ bf16  g_xln[MTOK*DIMC];   // tiled, K=256
__device__ bf16  g_h  [MTOK*4*DIMC]; // tiled, K=1024
__device__ bf16 g_bWq [DIMC*DIMC];
__device__ bf16 g_bWkv[2*DIMC*DIMC];
__device__ bf16 g_bWp [DIMC*DIMC];
__device__ bf16 g_bW1 [4*DIMC*DIMC];
__device__ bf16 g_bW2 [4*DIMC*DIMC];
__device__ float g_bm[4*8*64*64];    // combined bias+mask table

// -------------------------- helpers ---------------------------------------
__device__ __forceinline__ uint32_t smem_u32(const void* p) {
    return (uint32_t)__cvta_generic_to_shared(p);
}
__device__ __forceinline__ void cp_async16_a(uint32_t smem_dst, const void* gmem_src) {
    asm volatile("cp.async.cg.shared.global [%0], [%1], 16;\n" :: "r"(smem_dst), "l"(gmem_src));
}
__device__ __forceinline__ void cp_commit() { asm volatile("cp.async.commit_group;\n"); }
__device__ __forceinline__ void cp_wait0()  { asm volatile("cp.async.wait_group 0;\n"); }
__device__ __forceinline__ void cp_wait1()  { asm volatile("cp.async.wait_group 1;\n"); }

__device__ __forceinline__ void bulk_g2s(uint32_t dst, const void* src, uint32_t bytes, uint32_t mbar) {
    asm volatile("cp.async.bulk.shared::cta.global.mbarrier::complete_tx::bytes [%0], [%1], %2, [%3];"
                 :: "r"(dst), "l"(src), "r"(bytes), "r"(mbar) : "memory");
}
__device__ __forceinline__ void mbar_init(uint32_t mbar, uint32_t cnt) {
    asm volatile("mbarrier.init.shared.b64 [%0], %1;" :: "r"(mbar), "r"(cnt) : "memory");
}
__device__ __forceinline__ void mbar_expect_tx(uint32_t mbar, uint32_t bytes) {
    asm volatile("mbarrier.arrive.expect_tx.shared.b64 _, [%0], %1;" :: "r"(mbar), "r"(bytes) : "memory");
}
__device__ __forceinline__ void mbar_arrive(uint32_t mbar) {
    asm volatile("mbarrier.arrive.shared.b64 _, [%0];" :: "r"(mbar) : "memory");
}
__device__ __forceinline__ void mbar_wait(uint32_t mbar, uint32_t parity) {
    asm volatile(
        "{\n\t.reg .pred P;\n\t"
        "WL%=:\n\t"
        "mbarrier.try_wait.parity.acquire.cta.shared::cta.b64 P, [%0], %1, 0x989680;\n\t"
        "@P bra WD%=;\n\t"
        "bra.uni WL%=;\n\t"
        "WD%=:\n\t}"
        :: "r"(mbar), "r"(parity) : "memory");
}

__device__ __forceinline__ void mma_bf16(float c[4], const uint32_t a[4], const uint32_t b[2]) {
    asm volatile(
        "mma.sync.aligned.m16n8k16.row.col.f32.bf16.bf16.f32 "
        "{%0,%1,%2,%3}, {%4,%5,%6,%7}, {%8,%9}, {%0,%1,%2,%3};"
        : "+f"(c[0]), "+f"(c[1]), "+f"(c[2]), "+f"(c[3])
        : "r"(a[0]), "r"(a[1]), "r"(a[2]), "r"(a[3]), "r"(b[0]), "r"(b[1]));
}
__device__ __forceinline__ void ldsm4(uint32_t& r0, uint32_t& r1, uint32_t& r2, uint32_t& r3, uint32_t addr) {
    asm volatile("ldmatrix.sync.aligned.m8n8.x4.shared.b16 {%0,%1,%2,%3}, [%4];"
        : "=r"(r0), "=r"(r1), "=r"(r2), "=r"(r3) : "r"(addr));
}
__device__ __forceinline__ void ldsm4t(uint32_t& r0, uint32_t& r1, uint32_t& r2, uint32_t& r3, uint32_t addr) {
    asm volatile("ldmatrix.sync.aligned.m8n8.x4.trans.shared.b16 {%0,%1,%2,%3}, [%4];"
        : "=r"(r0), "=r"(r1), "=r"(r2), "=r"(r3) : "r"(addr));
}
__device__ __forceinline__ uint32_t pack_bf16(float lo, float hi) {
    uint32_t r;
    asm("cvt.rn.bf16x2.f32 %0, %1, %2;" : "=r"(r) : "f"(hi), "f"(lo));
    return r;
}
__device__ __forceinline__ float warp_sum(float v) {
    #pragma unroll
    for (int o = 16; o; o >>= 1) v += __shfl_xor_sync(0xffffffffu, v, o);
    return v;
}

// ------------- weight conversion (tiled) + bm-table build (y==5) -----------
__global__ void __launch_bounds__(256) convert_weights(
    const float* __restrict__ Wq, const float* __restrict__ Wkv,
    const float* __restrict__ Wp, const float* __restrict__ W1,
    const float* __restrict__ W2, const float* __restrict__ rpb)
{
    int which = blockIdx.y;
    if (which == 5) {        // build bias+mask table (32 cls*head planes)
        for (int f = blockIdx.x * 256 + threadIdx.x; f < 4 * 8 * 4096; f += gridDim.x * 256) {
            int plane = f >> 12, e = f & 4095;
            int cls = plane >> 3, head = plane & 7;
            int lastR = cls & 1, lastC = (cls >> 1) & 1;
            int i = e >> 6, j = e & 63;
            int ri = i >> 3, ci = i & 7, rj = j >> 3, cj = j & 7;
            int rel = (ri - rj + 7) * 15 + (ci - cj + 7);
            float a = rpb[rel * 8 + head];
            int liR = lastR ? (ri < 4 ? 1 : 2) : 0;
            int liC = lastC ? (ci < 4 ? 1 : 2) : 0;
            int ljR = lastR ? (rj < 4 ? 1 : 2) : 0;
            int ljC = lastC ? (cj < 4 ? 1 : 2) : 0;
            if (liR * 3 + liC != ljR * 3 + ljC) a -= 100.f;
            g_bm[f] = a;
        }
        return;
    }
    const float* src; bf16* dst; int N, K;
    if      (which == 0) { src = Wq;  dst = g_bWq;  N = 256;  K = 256;  }
    else if (which == 1) { src = Wkv; dst = g_bWkv; N = 512;  K = 256;  }
    else if (which == 2) { src = Wp;  dst = g_bWp;  N = 256;  K = 256;  }
    else if (which == 3) { src = W1;  dst = g_bW1;  N = 1024; K = 256;  }
    else                 { src = W2;  dst = g_bW2;  N = 256;  K = 1024; }
    int Kp8 = K >> 3;
    int nchunks = N * Kp8;
    const float4* src4 = (const float4*)src;
    char* dc = (char*)dst;
    for (int f = blockIdx.x * 256 + threadIdx.x; f < nchunks; f += gridDim.x * 256) {
        int nrow = f / Kp8;
        int ch0  = (f - nrow * Kp8) * 8;
        float4 v0 = src4[f * 2], v1 = src4[f * 2 + 1];
        uint4 o;
        o.x = pack_bf16(v0.x, v0.y); o.y = pack_bf16(v0.z, v0.w);
        o.z = pack_bf16(v1.x, v1.y); o.w = pack_bf16(v1.z, v1.w);
        int row = nrow & 127;
        size_t off = ((size_t)(nrow >> 7) * (K >> 5) + (ch0 >> 5)) * 8192
                   + row * 64 + ((((ch0 >> 3) & 3) ^ ((row >> 1) & 3)) * 16);
        *(uint4*)(dc + off) = o;
    }
}

// ---------- LN + cyclic shift + window partition (warp/token, tiled out) ---
__global__ void __launch_bounds__(256) ln_shift_part(
    const float* __restrict__ x0, const float* __restrict__ x1,
    const float* __restrict__ g0, const float* __restrict__ b0,
    const float* __restrict__ g1, const float* __restrict__ b1)
{
    int warp = threadIdx.x >> 5, lane = threadIdx.x & 31;
    int outTok = blockIdx.x * 8 + warp;
    int which  = blockIdx.y;
    int win = outTok >> 6, n = outTok & 63;
    int b   = win >> 6,  nw = win & 63;
    int y = ((nw >> 3) * WSZ + (n >> 3) + SHIFTW) & 63;
    int x = ((nw & 7) * WSZ + (n & 7) + SHIFTW) & 63;
    const float4* src4 = (const float4*)((which ? x1 : x0) + (size_t)(b * 4096 + y * 64 + x) * DIMC);
    char* dstc = (char*)(which ? g_x1w : g_x0w);
    const float4* gg4 = (const float4*)(which ? g1 : g0);
    const float4* bb4 = (const float4*)(which ? b1 : b0);

    float4 v0 = src4[lane * 2], v1 = src4[lane * 2 + 1];
    float s = v0.x + v0.y + v0.z + v0.w + v1.x + v1.y + v1.z + v1.w;
    float mean = warp_sum(s) * (1.f / 256.f);
    float d0 = v0.x - mean, d1 = v0.y - mean, d2 = v0.z - mean, d3 = v0.w - mean;
    float d4 = v1.x - mean, d5 = v1.y - mean, d6 = v1.z - mean, d7 = v1.w - mean;
    float vv = d0*d0 + d1*d1 + d2*d2 + d3*d3 + d4*d4 + d5*d5 + d6*d6 + d7*d7;
    float r = rsqrtf(warp_sum(vv) * (1.f / 256.f) + 1e-5f);
    float4 ga = gg4[lane * 2], gb = gg4[lane * 2 + 1];
    float4 ba = bb4[lane * 2], bb = bb4[lane * 2 + 1];
    uint4 o;
    o.x = pack_bf16(d0 * r * ga.x + ba.x, d1 * r * ga.y + ba.y);
    o.y = pack_bf16(d2 * r * ga.z + ba.z, d3 * r * ga.w + ba.w);
    o.z = pack_bf16(d4 * r * gb.x + bb.x, d5 * r * gb.y + bb.y);
    o.w = pack_bf16(d6 * r * gb.z + bb.z, d7 * r * gb.w + bb.w);
    int row = outTok & 127;
    size_t off = ((size_t)(outTok >> 7) * 8 + (lane >> 2)) * 8192
               + row * 64 + (((lane & 3) ^ ((row >> 1) & 3)) * 16);
    *(uint4*)(dstc + off) = o;
}

// ---------------- plain LN of g_x (fp32) -> g_xln (tiled bf16) -------------
__global__ void __launch_bounds__(256) ln_plain(
    const float* __restrict__ g2, const float* __restrict__ b2)
{
    int warp = threadIdx.x >> 5, lane = threadIdx.x & 31;
    int tok = blockIdx.x * 8 + warp;
    const float4* src4 = (const float4*)(g_x + (size_t)tok * DIMC);
    char* dstc = (char*)g_xln;
    const float4* gg4 = (const float4*)g2;
    const float4* bb4 = (const float4*)b2;

    float4 v0 = src4[lane * 2], v1 = src4[lane * 2 + 1];
    float s = v0.x + v0.y + v0.z + v0.w + v1.x + v1.y + v1.z + v1.w;
    float mean = warp_sum(s) * (1.f / 256.f);
    float d0 = v0.x - mean, d1 = v0.y - mean, d2 = v0.z - mean, d3 = v0.w - mean;
    float d4 = v1.x - mean, d5 = v1.y - mean, d6 = v1.z - mean, d7 = v1.w - mean;
    float vv = d0*d0 + d1*d1 + d2*d2 + d3*d3 + d4*d4 + d5*d5 + d6*d6 + d7*d7;
    float r = rsqrtf(warp_sum(vv) * (1.f / 256.f) + 1e-5f);
    float4 ga = gg4[lane * 2], gb = gg4[lane * 2 + 1];
    float4 ba = bb4[lane * 2], bb = bb4[lane * 2 + 1];
    uint4 o;
    o.x = pack_bf16(d0 * r * ga.x + ba.x, d1 * r * ga.y + ba.y);
    o.y = pack_bf16(d2 * r * ga.z + ba.z, d3 * r * ga.w + ba.w);
    o.z = pack_bf16(d4 * r * gb.x + bb.x, d5 * r * gb.y + bb.y);
    o.w = pack_bf16(d6 * r * gb.z + bb.z, d7 * r * gb.w + bb.w);
    int row = tok & 127;
    size_t off = ((size_t)(tok >> 7) * 8 + (lane >> 2)) * 8192
               + row * 64 + (((lane & 3) ^ ((row >> 1) & 3)) * 16);
    *(uint4*)(dstc + off) = o;
}

// ----------------------- bf16 tensor-core GEMMs ----------------------------
#define GEMM_SMEM (3*32768)

template<int MODE>
__device__ __forceinline__ void emit_pair(int m, int c0, float v0, float v1,
    float b0, float b1, const float* __restrict__ extra, float* __restrict__ out)
{
    v0 += b0;
    v1 += b1;
    if (MODE == 0) {
        v0 *= QSCALE; v1 *= QSCALE;
        int win = m >> 6, n = m & 63, hd = c0 >> 5, d = c0 & 31;
        uint32_t* p = (uint32_t*)g_q + ((((size_t)win * 8 + hd) * 64 + n) * 32 + d) / 2;
        *p = pack_bf16(v0, v1);
    } else if (MODE == 1) {
        int win = m >> 6, n = m & 63;
        int c2 = c0 & 255, hd = c2 >> 5, d = c2 & 31;
        size_t idx = ((((size_t)win * 8 + hd) * 64 + n) * 32 + d) / 2;
        uint32_t* p = (c0 < 256 ? (uint32_t*)g_k : (uint32_t*)g_v) + idx;
        *p = pack_bf16(v0, v1);
    } else if (MODE == 2) {
        int win = m >> 6, n = m & 63;
        int b = win >> 6, nw = win & 63;
        int y = ((nw >> 3) * WSZ + (n >> 3) + SHIFTW) & 63;
        int x = ((nw & 7) * WSZ + (n & 7) + SHIFTW) & 63;
        size_t t = ((size_t)(b * 4096 + y * 64 + x)) * DIMC + c0;
        float2 e = *(const float2*)&extra[t];
        *(float2*)&g_x[t] = make_float2(e.x + v0, e.y + v1);
    } else if (MODE == 3) {
        v0 = 0.5f * v0 * (1.f + erff(v0 * 0.70710678118654752f));
        v1 = 0.5f * v1 * (1.f + erff(v1 * 0.70710678118654752f));
        int row = m & 127;
        size_t off = ((size_t)(m >> 7) * 32 + (c0 >> 5)) * 8192 + row * 64
                   + ((((c0 >> 3) & 3) ^ ((row >> 1) & 3)) * 16) + (c0 & 7) * 2;
        *(uint32_t*)((char*)g_h + off) = pack_bf16(v0, v1);
    } else {
        size_t t = (size_t)m * DIMC + c0;
        float2 r = *(const float2*)&g_x[t];
        *(float2*)&out[t] = make_float2(r.x + v0, r.y + v1);
    }
}

struct GemmCtx {
    int rA, rB, aCh, bCh, aSwz, bSwz;
    uint32_t Sb, mbF, mbE;
};

__device__ __forceinline__ void gemm_mainloop(
    const GemmCtx& cx, const char* Ac, const char* Wc,
    size_t aT0, size_t wT0, int nK, int tid, float acc[4][4][4])
{
    if (tid == 0) {
        #pragma unroll
        for (int st = 0; st < 3; st++) {
            mbar_expect_tx(cx.mbF + st * 8, 32768);
            bulk_g2s(cx.Sb + st * 32768,         Ac + (aT0 + st * 2) * 8192, 16384, cx.mbF + st * 8);
            bulk_g2s(cx.Sb + st * 32768 + 16384, Wc + (wT0 + st * 2) * 8192, 16384, cx.mbF + st * 8);
        }
    }
    for (int s = 0; s < nK; ++s) {
        int q = s / 3;
        int slot = s - q * 3;
        mbar_wait(cx.mbF + slot * 8, (uint32_t)(q & 1));

        uint32_t stA = cx.Sb + slot * 32768;
        uint32_t stW = stA + 16384;
        #pragma unroll
        for (int ts = 0; ts < 2; ++ts) {
            uint32_t tA = stA + ts * 8192;
            uint32_t tW = stW + ts * 8192;
            #pragma unroll
            for (int kk = 0; kk < 2; ++kk) {
                uint32_t aF[4][4], bF[4][2];
                uint32_t aOff = ((kk * 2 + cx.aCh) ^ cx.aSwz) * 16;
                uint32_t bOff = ((kk * 2 + cx.bCh) ^ cx.bSwz) * 16;
                #pragma unroll
                for (int mi = 0; mi < 4; mi++)
                    ldsm4(aF[mi][0], aF[mi][1], aF[mi][2], aF[mi][3],
                          tA + (cx.rA + mi * 16) * 64 + aOff);
                ldsm4(bF[0][0], bF[0][1], bF[1][0], bF[1][1], tW + cx.rB * 64 + bOff);
                ldsm4(bF[2][0], bF[2][1], bF[3][0], bF[3][1], tW + (cx.rB + 16) * 64 + bOff);
                #pragma unroll
                for (int mi = 0; mi < 4; mi++)
                    #pragma unroll
                    for (int ni = 0; ni < 4; ni++)
                        mma_bf16(acc[mi][ni], aF[mi], bF[ni]);
            }
        }
        mbar_arrive(cx.mbE + slot * 8);
        if (tid == 0 && s + 3 < nK) {
            mbar_wait(cx.mbE + slot * 8, (uint32_t)(q & 1));
            mbar_expect_tx(cx.mbF + slot * 8, 32768);
            bulk_g2s(cx.Sb + slot * 32768,         Ac + (aT0 + (s + 3) * 2) * 8192, 16384, cx.mbF + slot * 8);
            bulk_g2s(cx.Sb + slot * 32768 + 16384, Wc + (wT0 + (s + 3) * 2) * 8192, 16384, cx.mbF + slot * 8);
        }
    }
}

__device__ __forceinline__ GemmCtx make_ctx(int tid, bf16* sm, uint64_t* s_full, uint64_t* s_empty) {
    int lane = tid & 31, warp = tid >> 5;
    int mWarp = (warp >> 2) * 64;
    int nWarp = (warp & 3) * 32;
    int mm = lane >> 3, r8 = lane & 7;
    GemmCtx cx;
    cx.rA = mWarp + (mm & 1) * 8 + r8;
    cx.rB = nWarp + (mm >> 1) * 8 + r8;
    cx.aCh = mm >> 1;
    cx.bCh = mm & 1;
    cx.aSwz = (cx.rA >> 1) & 3;
    cx.bSwz = (cx.rB >> 1) & 3;
    cx.Sb  = smem_u32(sm);
    cx.mbF = smem_u32(s_full);
    cx.mbE = smem_u32(s_empty);
    if (tid == 0) {
        #pragma unroll
        for (int st = 0; st < 3; st++) {
            mbar_init(cx.mbF + st * 8, 1);
            mbar_init(cx.mbE + st * 8, 256);
        }
    }
    __syncthreads();
    return cx;
}

template<int MODE>
__global__ void __launch_bounds__(256, 2) mma_gemm(
    const bf16* __restrict__ W, const float* __restrict__ bias,
    int K, const float* __restrict__ extra, float* __restrict__ out)
{
    extern __shared__ bf16 sm[];
    __shared__ uint64_t s_full[3];
    __shared__ uint64_t s_empty[3];
    const bf16* A = (MODE == 2) ? g_ao :
                    (MODE == 3) ? g_xln : g_h;

    int tid  = threadIdx.x;
    int lane = tid & 31, warp = tid >> 5;
    int gr = lane >> 2, lc = lane & 3;
    GemmCtx cx = make_ctx(tid, sm, s_full, s_empty);

    int rowBase = blockIdx.y * 128;
    int colBase = blockIdx.x * 128;
    int nK = K >> 6;
    float acc[4][4][4];
    #pragma unroll
    for (int mi = 0; mi < 4; mi++)
        #pragma unroll
        for (int ni = 0; ni < 4; ni++)
            #pragma unroll
            for (int e = 0; e < 4; e++) acc[mi][ni][e] = 0.f;

    gemm_mainloop(cx, (const char*)A, (const char*)W,
                  (size_t)blockIdx.y * (K >> 5), (size_t)blockIdx.x * (K >> 5),
                  nK, tid, acc);

    int mWarp = (warp >> 2) * 64;
    int nWarp = (warp & 3) * 32;
    float2 bN[4];
    #pragma unroll
    for (int ni = 0; ni < 4; ni++)
        bN[ni] = __ldg((const float2*)&bias[colBase + nWarp + ni * 8 + lc * 2]);

    #pragma unroll
    for (int mi = 0; mi < 4; mi++) {
        int r0 = rowBase + mWarp + mi * 16 + gr;
        #pragma unroll
        for (int ni = 0; ni < 4; ni++) {
            int c0 = colBase + nWarp + ni * 8 + lc * 2;
            emit_pair<MODE>(r0,     c0, acc[mi][ni][0], acc[mi][ni][1], bN[ni].x, bN[ni].y, extra, out);
            emit_pair<MODE>(r0 + 8, c0, acc[mi][ni][2], acc[mi][ni][3], bN[ni].x, bN[ni].y, extra, out);
        }
    }
}

// fused q + kv projection: CTAs [0,1024) do q, [1024,3072) do kv
__global__ void __launch_bounds__(256, 2) mma_gemm_qkv(
    const bf16* __restrict__ Wq, const float* __restrict__ bq,
    const bf16* __restrict__ Wkv, const float* __restrict__ bkv)
{
    extern __shared__ bf16 sm[];
    __shared__ uint64_t s_full[3];
    __shared__ uint64_t s_empty[3];

    int tid  = threadIdx.x;
    int lane = tid & 31, warp = tid >> 5;
    int gr = lane >> 2, lc = lane & 3;
    GemmCtx cx = make_ctx(tid, sm, s_full, s_empty);

    bool isQ = blockIdx.x < 1024;
    int bid  = isQ ? blockIdx.x : blockIdx.x - 1024;
    const bf16* A = isQ ? g_x1w : g_x0w;
    const bf16* W = isQ ? Wq : Wkv;
    const float* bias = isQ ? bq : bkv;
    int tx = isQ ? (bid & 1) : (bid & 3);
    int ty = isQ ? (bid >> 1) : (bid >> 2);
    int rowBase = ty * 128;
    int colBase = tx * 128;

    float acc[4][4][4];
    #pragma unroll
    for (int mi = 0; mi < 4; mi++)
        #pragma unroll
        for (int ni = 0; ni < 4; ni++)
            #pragma unroll
            for (int e = 0; e < 4; e++) acc[mi][ni][e] = 0.f;

    gemm_mainloop(cx, (const char*)A, (const char*)W,
                  (size_t)ty * 8, (size_t)tx * 8, 4, tid, acc);

    int mWarp = (warp >> 2) * 64;
    int nWarp = (warp & 3) * 32;
    float2 bN[4];
    #pragma unroll
    for (int ni = 0; ni < 4; ni++)
        bN[ni] = __ldg((const float2*)&bias[colBase + nWarp + ni * 8 + lc * 2]);

    if (isQ) {
        #pragma unroll
        for (int mi = 0; mi < 4; mi++) {
            int r0 = rowBase + mWarp + mi * 16 + gr;
            #pragma unroll
            for (int ni = 0; ni < 4; ni++) {
                int c0 = colBase + nWarp + ni * 8 + lc * 2;
                emit_pair<0>(r0,     c0, acc[mi][ni][0], acc[mi][ni][1], bN[ni].x, bN[ni].y, nullptr, nullptr);
                emit_pair<0>(r0 + 8, c0, acc[mi][ni][2], acc[mi][ni][3], bN[ni].x, bN[ni].y, nullptr, nullptr);
            }
        }
    } else {
        #pragma unroll
        for (int mi = 0; mi < 4; mi++) {
            int r0 = rowBase + mWarp + mi * 16 + gr;
            #pragma unroll
            for (int ni = 0; ni < 4; ni++) {
                int c0 = colBase + nWarp + ni * 8 + lc * 2;
                emit_pair<1>(r0,     c0, acc[mi][ni][0], acc[mi][ni][1], bN[ni].x, bN[ni].y, nullptr, nullptr);
                emit_pair<1>(r0 + 8, c0, acc[mi][ni][2], acc[mi][ni][3], bN[ni].x, bN[ni].y, nullptr, nullptr);
            }
        }
    }
}

// ------------- tensor-core attention: warp = (head), block = (win, half) ---
#define ATTN_HEAD_BYTES 9216          // 4096 (K) + 5120 (V)
#define ATTN_SMEM (8*ATTN_HEAD_BYTES) // 73728
__global__ void __launch_bounds__(256) attn_kernel()
{
    extern __shared__ char smattn[];

    int blk  = blockIdx.x;
    int win  = blk >> 1, half = blk & 1;
    int tid  = threadIdx.x;
    int lane = tid & 31, head = tid >> 5;
    int gr = lane >> 2, lc = lane & 3;

    size_t hb = ((size_t)win * 8 + head) * 64 * 32;
    const uint32_t* q32 = (const uint32_t*)(g_q + hb);

    uint32_t ksB = smem_u32(smattn) + head * ATTN_HEAD_BYTES;
    uint32_t vsB = ksB + 4096;

    // stage K (SW64 swizzle), commit; then V (80B rows), commit.
    {
        const bf16* ksrc = g_k + hb;
        #pragma unroll
        for (int it = 0; it < 8; it++) {
            int c = it * 32 + lane;
            int row = c >> 2, k8 = (c & 3) * 8;
            uint32_t dst = ksB + row * 64 + ((((c & 3) ^ ((row >> 1) & 3))) * 16);
            cp_async16_a(dst, ksrc + row * 32 + k8);
        }
        cp_commit();
        const bf16* vsrc = g_v + hb;
        #pragma unroll
        for (int it = 0; it < 8; it++) {
            int c = it * 32 + lane;
            int row = c >> 2, k8 = (c & 3) * 8;
            cp_async16_a(vsB + row * 80 + k8 * 2, vsrc + row * 32 + k8);
        }
        cp_commit();
    }

    float sacc[2][8][4];
    #pragma unroll
    for (int mt = 0; mt < 2; mt++)
        #pragma unroll
        for (int nt = 0; nt < 8; nt++)
            #pragma unroll
            for (int e = 0; e < 4; e++) sacc[mt][nt][e] = 0.f;

    int mm = lane >> 3, r8 = lane & 7;
    int rowK16 = (mm >> 1) * 8 + r8;
    int bCh = mm & 1;

    cp_wait1();
    __syncwarp();

    #pragma unroll
    for (int kt = 0; kt < 2; kt++) {
        uint32_t aQ[2][4];
        #pragma unroll
        for (int mt = 0; mt < 2; mt++) {
            int i0 = half * 32 + mt * 16 + gr;
            aQ[mt][0] = q32[i0 * 16 + 8 * kt + lc];
            aQ[mt][1] = q32[(i0 + 8) * 16 + 8 * kt + lc];
            aQ[mt][2] = q32[i0 * 16 + 8 * kt + lc + 4];
            aQ[mt][3] = q32[(i0 + 8) * 16 + 8 * kt + lc + 4];
        }
        uint32_t bK[8][2];
        #pragma unroll
        for (int p = 0; p < 4; p++) {
            int fr = p * 16 + rowK16;
            uint32_t off = ((uint32_t)((kt * 2 + bCh) ^ ((fr >> 1) & 3))) * 16;
            ldsm4(bK[2*p][0], bK[2*p][1], bK[2*p+1][0], bK[2*p+1][1],
                  ksB + fr * 64 + off);
        }
        #pragma unroll
        for (int mt = 0; mt < 2; mt++)
            #pragma unroll
            for (int nt = 0; nt < 8; nt++)
                mma_bf16(sacc[mt][nt], aQ[mt], bK[nt]);
    }

    // ---- add precomputed bias+mask table ----
    int nw  = win & 63;
    int cls = (((nw >> 3) == 7) ? 1 : 0) | (((nw & 7) == 7) ? 2 : 0);
    const float* T = g_bm + ((cls * 8 + head) << 12);
    #pragma unroll
    for (int mt = 0; mt < 2; mt++) {
        #pragma unroll
        for (int re = 0; re < 2; re++) {
            int i = half * 32 + mt * 16 + gr + 8 * re;
            const float2* Trow = (const float2*)(T + i * 64) + lc;
            #pragma unroll
            for (int nt = 0; nt < 8; nt++) {
                float2 t = __ldg(&Trow[nt * 4]);
                sacc[mt][nt][re * 2]     += t.x;
                sacc[mt][nt][re * 2 + 1] += t.y;
            }
        }
    }

    float inv[2][2];
    #pragma unroll
    for (int mt = 0; mt < 2; mt++) {
        #pragma unroll
        for (int re = 0; re < 2; re++) {
            float mx = -1e30f;
            #pragma unroll
            for (int nt = 0; nt < 8; nt++) {
                mx = fmaxf(mx, sacc[mt][nt][re * 2]);
                mx = fmaxf(mx, sacc[mt][nt][re * 2 + 1]);
            }
            mx = fmaxf(mx, __shfl_xor_sync(0xffffffffu, mx, 1));
            mx = fmaxf(mx, __shfl_xor_sync(0xffffffffu, mx, 2));
            float sm = 0.f;
            #pragma unroll
            for (int nt = 0; nt < 8; nt++) {
                float e0 = __expf(sacc[mt][nt][re * 2]     - mx);
                float e1 = __expf(sacc[mt][nt][re * 2 + 1] - mx);
                sacc[mt][nt][re * 2]     = e0;
                sacc[mt][nt][re * 2 + 1] = e1;
                sm += e0 + e1;
            }
            sm += __shfl_xor_sync(0xffffffffu, sm, 1);
            sm += __shfl_xor_sync(0xffffffffu, sm, 2);
            inv[mt][re] = 1.f / sm;
        }
    }

    cp_wait0();
    __syncwarp();

    int vmm = lane >> 3, vr8 = lane & 7;
    int vRow = (vmm & 1) * 8 + vr8, vNd = vmm >> 1;

    float oacc[2][4][4];
    #pragma unroll
    for (int mt = 0; mt < 2; mt++)
        #pragma unroll
        for (int nt = 0; nt < 4; nt++)
            #pragma unroll
            for (int e = 0; e < 4; e++) oacc[mt][nt][e] = 0.f;

    #pragma unroll
    for (int kt = 0; kt < 4; kt++) {
        uint32_t aP[2][4];
        #pragma unroll
        for (int mt = 0; mt < 2; mt++) {
            aP[mt][0] = pack_bf16(sacc[mt][2 * kt][0],     sacc[mt][2 * kt][1]);
            aP[mt][1] = pack_bf16(sacc[mt][2 * kt][2],     sacc[mt][2 * kt][3]);
            aP[mt][2] = pack_bf16(sacc[mt][2 * kt + 1][0], sacc[mt][2 * kt + 1][1]);
            aP[mt][3] = pack_bf16(sacc[mt][2 * kt + 1][2], sacc[mt][2 * kt + 1][3]);
        }
        uint32_t bV[4][2];
        #pragma unroll
        for (int p = 0; p < 2; p++) {
            uint32_t addr = vsB + (((16 * kt + vRow) * 40) + (p * 2 + vNd) * 8) * 2;
            ldsm4t(bV[2*p][0], bV[2*p][1], bV[2*p+1][0], bV[2*p+1][1], addr);
        }
        #pragma unroll
        for (int mt = 0; mt < 2; mt++)
            #pragma unroll
            for (int nt = 0; nt < 4; nt++)
                mma_bf16(oacc[mt][nt], aP[mt], bV[nt]);
    }

    // epilogue: normalize, pack, store to TILED g_ao
    char* aoc = (char*)g_ao;
    #pragma unroll
    for (int mt = 0; mt < 2; mt++) {
        int i0 = half * 32 + mt * 16 + gr;
        int row0 = (win & 1) * 64 + i0;
        int sw = (row0 >> 1) & 3;
        size_t base = ((size_t)(win >> 1) * 8 + head) * 8192 + (size_t)row0 * 64 + lc * 4;
        float v0 = inv[mt][0], v1 = inv[mt][1];
        #pragma unroll
        for (int nt = 0; nt < 4; nt++) {
            uint32_t p0 = pack_bf16(oacc[mt][nt][0] * v0, oacc[mt][nt][1] * v0);
            uint32_t p1 = pack_bf16(oacc[mt][nt][2] * v1, oacc[mt][nt][3] * v1);
            size_t off = base + (size_t)((nt ^ sw) * 16);
            *(uint32_t*)(aoc + off)       = p0;
            *(uint32_t*)(aoc + off + 512) = p1;   // +8 rows * 64B
        }
    }
}

// ------------------------------- launcher ----------------------------------
extern "C" void kernel_launch(void* const* d_in, const int* in_sizes, int n_in,
                              void* d_out, int out_size)
{
    const float* x0   = (const float*)d_in[0];
    const float* x1   = (const float*)d_in[1];
    const float* g1_0 = (const float*)d_in[2];
    const float* b1_0 = (const float*)d_in[3];
    const float* g1_1 = (const float*)d_in[4];
    const float* b1_1 = (const float*)d_in[5];
    const float* Wq   = (const float*)d_in[6];
    const float* bq   = (const float*)d_in[7];
    const float* Wkv  = (const float*)d_in[8];
    const float* bkv  = (const float*)d_in[9];
    const float* rpb  = (const float*)d_in[10];
    const float* Wp   = (const float*)d_in[11];
    const float* bp   = (const float*)d_in[12];
    const float* g2   = (const float*)d_in[13];
    const float* b2   = (const float*)d_in[14];
    const float* Wfc1 = (const float*)d_in[15];
    const float* bfc1 = (const float*)d_in[16];
    const float* Wfc2 = (const float*)d_in[17];
    const float* bfc2 = (const float*)d_in[18];
    float* out = (float*)d_out;

    bf16 *bWq, *bWkv, *bWp, *bW1, *bW2;
    cudaGetSymbolAddress((void**)&bWq,  g_bWq);
    cudaGetSymbolAddress((void**)&bWkv, g_bWkv);
    cudaGetSymbolAddress((void**)&bWp,  g_bWp);
    cudaGetSymbolAddress((void**)&bW1,  g_bW1);
    cudaGetSymbolAddress((void**)&bW2,  g_bW2);

    cudaFuncSetAttribute(mma_gemm_qkv, cudaFuncAttributeMaxDynamicSharedMemorySize, GEMM_SMEM);
    cudaFuncSetAttribute(mma_gemm<2>, cudaFuncAttributeMaxDynamicSharedMemorySize, GEMM_SMEM);
    cudaFuncSetAttribute(mma_gemm<3>, cudaFuncAttributeMaxDynamicSharedMemorySize, GEMM_SMEM);
    cudaFuncSetAttribute(mma_gemm<4>, cudaFuncAttributeMaxDynamicSharedMemorySize, GEMM_SMEM);
    cudaFuncSetAttribute(attn_kernel, cudaFuncAttributeMaxDynamicSharedMemorySize, ATTN_SMEM);

    convert_weights<<<dim3(128, 6), 256>>>(Wq, Wkv, Wp, Wfc1, Wfc2, rpb);
    ln_shift_part<<<dim3(MTOK / 8, 2), 256>>>(x0, x1, g1_0, b1_0, g1_1, b1_1);
    mma_gemm_qkv<<<3072, 256, GEMM_SMEM>>>(bWq, bq, bWkv, bkv);
    attn_kernel<<<2048, 256, ATTN_SMEM>>>();
    mma_gemm<2><<<dim3(2, 512), 256, GEMM_SMEM>>>(bWp,  bp,   256,  x1,      nullptr);
    ln_plain<<<MTOK / 8, 256>>>(g2, b2);
    mma_gemm<3><<<dim3(8, 512), 256, GEMM_SMEM>>>(bW1,  bfc1, 256,  nullptr, nullptr);
    mma_gemm<4><<<dim3(2, 512), 256, GEMM_SMEM>>>(bW2,  bfc2, 1024, nullptr, out);
}